// round 9
// baseline (speedup 1.0000x reference)
#include <cuda_runtime.h>
#include <cstdint>

// out[512,128] = X[512, 1048576] @ W[1048576, 128]   fp32 in/out, tf32 mma.sync
//
// Pure sm_80-compatible PTX (mma.sync + cp.async): compiles under the plain
// compute_103 target that broke the tcgen05 build in R8.

#define RED_LEN   1048576
#define M_ROWS    512
#define N_COLS    128
#define KTILE     32
#define NUM_KG    37          // split-K groups (x 4 M-groups = 148 CTAs)
#define NTHREADS  256         // 8 warps, warp grid 2(m) x 4(n), warp tile 64x32
#define STAGES    4
#define STAGE_BYTES 32768     // A 16KB (128x32 f32) + B 16KB (32x128 f32)
#define SMEM_TOTAL (STAGES * STAGE_BYTES)   // 131072

// tiles: 32768 k-tiles total = 37*885 + 23
#define BASE_TILES 885
#define REM_TILES  23

__device__ float g_scratch[(size_t)NUM_KG * M_ROWS * N_COLS];   // 9.7 MB partials

// ---------------- helpers ----------------
__device__ __forceinline__ uint32_t smem_u32(const void* p) {
    uint32_t a;
    asm("{ .reg .u64 t; cvta.to.shared.u64 t, %1; cvt.u32.u64 %0, t; }" : "=r"(a) : "l"(p));
    return a;
}
__device__ __forceinline__ uint32_t f2tf32(float x) {   // round-to-nearest tf32 (unbiased)
    uint32_t u;
    asm("cvt.rna.tf32.f32 %0, %1;" : "=r"(u) : "f"(x));
    return u;
}
__device__ __forceinline__ void cp16(uint32_t dst_smem, const void* src) {
    asm volatile("cp.async.cg.shared.global [%0], [%1], 16;" :: "r"(dst_smem), "l"(src) : "memory");
}
__device__ __forceinline__ float4 lds128(uint32_t addr) {
    float4 v;
    asm volatile("ld.shared.v4.f32 {%0,%1,%2,%3}, [%4];"
                 : "=f"(v.x), "=f"(v.y), "=f"(v.z), "=f"(v.w) : "r"(addr));
    return v;
}
__device__ __forceinline__ float lds32(uint32_t addr) {
    float v;
    asm volatile("ld.shared.f32 %0, [%1];" : "=f"(v) : "r"(addr));
    return v;
}
__device__ __forceinline__ void mma_tf32(float d[4], uint32_t a0, uint32_t a1, uint32_t a2, uint32_t a3,
                                         uint32_t b0, uint32_t b1) {
    asm volatile(
        "mma.sync.aligned.m16n8k8.row.col.f32.tf32.tf32.f32 "
        "{%0,%1,%2,%3}, {%4,%5,%6,%7}, {%8,%9}, {%0,%1,%2,%3};"
        : "+f"(d[0]), "+f"(d[1]), "+f"(d[2]), "+f"(d[3])
        : "r"(a0), "r"(a1), "r"(a2), "r"(a3), "r"(b0), "r"(b1));
}

// ---------------- main GEMM ----------------
// Fragment k-permutation (A and B consistent): physical mma k-pos p at kstep j
// holds global k = kbase + 8*(p&3) + 2*j + (p>>2).  => thread (c=lane&3) needs
// A[row, 8c..8c+7] (contiguous, 2x LDS.128) and B[8c+2j+{0,1}, n].
//
// SMEM swizzles (16B-chunk XOR, matched in cp.async stores and LDS reads):
//   A (128B rows, chunks x=0..7):  x' = x ^ (row & 7)
//   B (512B rows, chunks x=0..31): x' = x ^ (((k>>3)&3) << 1)
// Both verified conflict-free for all read phases.

__global__ void __launch_bounds__(NTHREADS, 1)
gemm_tf32_mmasync(const float* __restrict__ X, const float* __restrict__ W) {
    extern __shared__ char smem[];
    const uint32_t sbase = smem_u32(smem);
    const int tid  = threadIdx.x;
    const int lane = tid & 31;
    const int wid  = tid >> 5;
    const int wm   = wid >> 2;          // 0..1  (m dimension, 64 rows each)
    const int wn   = wid & 3;           // 0..3  (n dimension, 32 cols each)
    const int c    = lane & 3;
    const int r4   = lane >> 2;

    const int bid = blockIdx.x;
    const int kg  = bid >> 2;           // 0..36 split-K group (4 CTAs share W in L2)
    const int mg  = bid & 3;            // 0..3  M-group (128 rows each)

    const int t0  = kg * BASE_TILES + (kg < REM_TILES ? kg : REM_TILES);
    const int cnt = BASE_TILES + (kg < REM_TILES ? 1 : 0);

    const float* Xb = X + (size_t)(mg * 128) * RED_LEN;

    // ---- async stage fill ----
    auto issue = [&](int stage, int tile) {
        const uint32_t sa = sbase + stage * STAGE_BYTES;
        const uint32_t sb = sa + 16384;
        const size_t kb = (size_t)(t0 + tile) * KTILE;
        #pragma unroll
        for (int i = 0; i < 4; ++i) {          // A: 1024 chunks (128 rows x 8)
            const int q = tid + NTHREADS * i;
            const int row = q >> 3, x = q & 7;
            cp16(sa + row * 128 + ((x ^ (row & 7)) << 4),
                 Xb + (size_t)row * RED_LEN + kb + x * 4);
        }
        #pragma unroll
        for (int i = 0; i < 4; ++i) {          // B: 1024 chunks (32 k-rows x 32)
            const int q = tid + NTHREADS * i;
            const int k = q >> 5, x = q & 31;
            cp16(sb + k * 512 + ((x ^ (((k >> 3) & 3) << 1)) << 4),
                 W + (kb + (size_t)k) * N_COLS + x * 4);
        }
    };

    // prologue: stages 0..2
    #pragma unroll
    for (int s = 0; s < STAGES - 1; ++s) {
        issue(s, s);   // cnt >= 885 >> 3, always valid
        asm volatile("cp.async.commit_group;" ::: "memory");
    }

    float d[4][4][4];
    #pragma unroll
    for (int a = 0; a < 4; ++a)
        #pragma unroll
        for (int b = 0; b < 4; ++b)
            #pragma unroll
            for (int e = 0; e < 4; ++e) d[a][b][e] = 0.f;

    for (int t = 0; t < cnt; ++t) {
        asm volatile("cp.async.wait_group 2;" ::: "memory");
        __syncthreads();

        const uint32_t sa = sbase + (t & (STAGES - 1)) * STAGE_BYTES;
        const uint32_t sb = sa + 16384;

        // ---- B fragments: bf[nt][j][{b0,b1}], k = 8c + 2j (+1) ----
        uint32_t bf[4][4][2];
        #pragma unroll
        for (int nt = 0; nt < 4; ++nt) {
            const int n = wn * 32 + nt * 8 + r4;
            const uint32_t baddr = sb + (((n >> 2) ^ (2 * c)) << 4) + (n & 3) * 4;
            #pragma unroll
            for (int j = 0; j < 4; ++j) {
                const int k0 = 8 * c + 2 * j;
                bf[nt][j][0] = f2tf32(lds32(baddr + k0 * 512));
                bf[nt][j][1] = f2tf32(lds32(baddr + (k0 + 1) * 512));
            }
        }

        // ---- A fragments + MMA, one 16-row pair-group (mt) at a time ----
        const uint32_t ch0 = ((2 * c) ^ r4) << 4;
        const uint32_t ch1 = ((2 * c + 1) ^ r4) << 4;
        #pragma unroll
        for (int mt = 0; mt < 4; ++mt) {
            const int R0 = wm * 64 + mt * 16 + r4;
            const uint32_t ab0 = sa + R0 * 128;        // row R0
            const uint32_t ab1 = ab0 + 8 * 128;        // row R0+8
            const float4 p0 = lds128(ab0 + ch0);       // k 8c..8c+3
            const float4 p1 = lds128(ab0 + ch1);       // k 8c+4..8c+7
            const float4 q0 = lds128(ab1 + ch0);
            const float4 q1 = lds128(ab1 + ch1);
            uint32_t a0r[8] = { f2tf32(p0.x), f2tf32(p0.y), f2tf32(p0.z), f2tf32(p0.w),
                                f2tf32(p1.x), f2tf32(p1.y), f2tf32(p1.z), f2tf32(p1.w) };
            uint32_t a1r[8] = { f2tf32(q0.x), f2tf32(q0.y), f2tf32(q0.z), f2tf32(q0.w),
                                f2tf32(q1.x), f2tf32(q1.y), f2tf32(q1.z), f2tf32(q1.w) };
            #pragma unroll
            for (int j = 0; j < 4; ++j) {
                const uint32_t A0 = a0r[2 * j],     A1 = a1r[2 * j];
                const uint32_t A2 = a0r[2 * j + 1], A3 = a1r[2 * j + 1];
                #pragma unroll
                for (int nt = 0; nt < 4; ++nt)
                    mma_tf32(d[mt][nt], A0, A1, A2, A3, bf[nt][j][0], bf[nt][j][1]);
            }
        }

        __syncthreads();
        if (t + STAGES - 1 < cnt) issue((t + STAGES - 1) & (STAGES - 1), t + STAGES - 1);
        asm volatile("cp.async.commit_group;" ::: "memory");
    }

    // ---- epilogue: write 128x128 partial to scratch[kg] ----
    float* outp = g_scratch + (size_t)kg * (M_ROWS * N_COLS);
    #pragma unroll
    for (int mt = 0; mt < 4; ++mt) {
        #pragma unroll
        for (int nt = 0; nt < 4; ++nt) {
            const int row = mg * 128 + wm * 64 + mt * 16 + r4;
            const int col = wn * 32 + nt * 8 + 2 * c;
            float2 v0 = make_float2(d[mt][nt][0], d[mt][nt][1]);
            float2 v1 = make_float2(d[mt][nt][2], d[mt][nt][3]);
            *reinterpret_cast<float2*>(outp + (size_t)row * N_COLS + col)       = v0;
            *reinterpret_cast<float2*>(outp + (size_t)(row + 8) * N_COLS + col) = v1;
        }
    }
}

// ---------------- deterministic 37-way reduction ----------------
__global__ void reduce_partials(float* __restrict__ out) {
    const int i = blockIdx.x * blockDim.x + threadIdx.x;   // 0 .. 65535
    float acc = 0.f;
    #pragma unroll
    for (int g = 0; g < NUM_KG; ++g)
        acc += g_scratch[(size_t)g * (M_ROWS * N_COLS) + i];
    out[i] = acc;
}

extern "C" void kernel_launch(void* const* d_in, const int* in_sizes, int n_in,
                              void* d_out, int out_size) {
    const float* X = (const float*)d_in[0];   // [512, 1024, 1024]
    const float* W = (const float*)d_in[1];   // [1024, 1024, 128]
    float* out = (float*)d_out;               // [512, 128]

    cudaFuncSetAttribute(gemm_tf32_mmasync, cudaFuncAttributeMaxDynamicSharedMemorySize, SMEM_TOTAL);
    gemm_tf32_mmasync<<<NUM_KG * 4, NTHREADS, SMEM_TOTAL>>>(X, W);
    reduce_partials<<<(M_ROWS * N_COLS) / 256, 256>>>(out);
}

// round 10
// speedup vs baseline: 1.0016x; 1.0016x over previous
#include <cuda_runtime.h>
#include <cstdint>

// out[512,128] = X[512, 1048576] @ W[1048576, 128]   fp32 in/out, tf32 mma.sync
//
// Pure sm_80-compatible PTX (mma.sync + cp.async): compiles under the plain
// compute_103 target that broke the tcgen05 build in R8.

#define RED_LEN   1048576
#define M_ROWS    512
#define N_COLS    128
#define KTILE     32
#define NUM_KG    37          // split-K groups (x 4 M-groups = 148 CTAs)
#define NTHREADS  256         // 8 warps, warp grid 2(m) x 4(n), warp tile 64x32
#define STAGES    4
#define STAGE_BYTES 32768     // A 16KB (128x32 f32) + B 16KB (32x128 f32)
#define SMEM_TOTAL (STAGES * STAGE_BYTES)   // 131072

// tiles: 32768 k-tiles total = 37*885 + 23
#define BASE_TILES 885
#define REM_TILES  23

__device__ float g_scratch[(size_t)NUM_KG * M_ROWS * N_COLS];   // 9.7 MB partials

// ---------------- helpers ----------------
__device__ __forceinline__ uint32_t smem_u32(const void* p) {
    uint32_t a;
    asm("{ .reg .u64 t; cvta.to.shared.u64 t, %1; cvt.u32.u64 %0, t; }" : "=r"(a) : "l"(p));
    return a;
}
__device__ __forceinline__ uint32_t f2tf32(float x) {   // round-to-nearest tf32 (unbiased)
    uint32_t u;
    asm("cvt.rna.tf32.f32 %0, %1;" : "=r"(u) : "f"(x));
    return u;
}
__device__ __forceinline__ void cp16(uint32_t dst_smem, const void* src) {
    asm volatile("cp.async.cg.shared.global [%0], [%1], 16;" :: "r"(dst_smem), "l"(src) : "memory");
}
__device__ __forceinline__ float4 lds128(uint32_t addr) {
    float4 v;
    asm volatile("ld.shared.v4.f32 {%0,%1,%2,%3}, [%4];"
                 : "=f"(v.x), "=f"(v.y), "=f"(v.z), "=f"(v.w) : "r"(addr));
    return v;
}
__device__ __forceinline__ float lds32(uint32_t addr) {
    float v;
    asm volatile("ld.shared.f32 %0, [%1];" : "=f"(v) : "r"(addr));
    return v;
}
__device__ __forceinline__ void mma_tf32(float d[4], uint32_t a0, uint32_t a1, uint32_t a2, uint32_t a3,
                                         uint32_t b0, uint32_t b1) {
    asm volatile(
        "mma.sync.aligned.m16n8k8.row.col.f32.tf32.tf32.f32 "
        "{%0,%1,%2,%3}, {%4,%5,%6,%7}, {%8,%9}, {%0,%1,%2,%3};"
        : "+f"(d[0]), "+f"(d[1]), "+f"(d[2]), "+f"(d[3])
        : "r"(a0), "r"(a1), "r"(a2), "r"(a3), "r"(b0), "r"(b1));
}

// ---------------- main GEMM ----------------
// Fragment k-permutation (A and B consistent): physical mma k-pos p at kstep j
// holds global k = kbase + 8*(p&3) + 2*j + (p>>2).  => thread (c=lane&3) needs
// A[row, 8c..8c+7] (contiguous, 2x LDS.128) and B[8c+2j+{0,1}, n].
//
// SMEM swizzles (16B-chunk XOR, matched in cp.async stores and LDS reads):
//   A (128B rows, chunks x=0..7):  x' = x ^ (row & 7)
//   B (512B rows, chunks x=0..31): x' = x ^ (((k>>3)&3) << 1)
// Both verified conflict-free for all read phases.

__global__ void __launch_bounds__(NTHREADS, 1)
gemm_tf32_mmasync(const float* __restrict__ X, const float* __restrict__ W) {
    extern __shared__ char smem[];
    const uint32_t sbase = smem_u32(smem);
    const int tid  = threadIdx.x;
    const int lane = tid & 31;
    const int wid  = tid >> 5;
    const int wm   = wid >> 2;          // 0..1  (m dimension, 64 rows each)
    const int wn   = wid & 3;           // 0..3  (n dimension, 32 cols each)
    const int c    = lane & 3;
    const int r4   = lane >> 2;

    const int bid = blockIdx.x;
    const int kg  = bid >> 2;           // 0..36 split-K group (4 CTAs share W in L2)
    const int mg  = bid & 3;            // 0..3  M-group (128 rows each)

    const int t0  = kg * BASE_TILES + (kg < REM_TILES ? kg : REM_TILES);
    const int cnt = BASE_TILES + (kg < REM_TILES ? 1 : 0);

    const float* Xb = X + (size_t)(mg * 128) * RED_LEN;

    // ---- async stage fill ----
    auto issue = [&](int stage, int tile) {
        const uint32_t sa = sbase + stage * STAGE_BYTES;
        const uint32_t sb = sa + 16384;
        const size_t kb = (size_t)(t0 + tile) * KTILE;
        #pragma unroll
        for (int i = 0; i < 4; ++i) {          // A: 1024 chunks (128 rows x 8)
            const int q = tid + NTHREADS * i;
            const int row = q >> 3, x = q & 7;
            cp16(sa + row * 128 + ((x ^ (row & 7)) << 4),
                 Xb + (size_t)row * RED_LEN + kb + x * 4);
        }
        #pragma unroll
        for (int i = 0; i < 4; ++i) {          // B: 1024 chunks (32 k-rows x 32)
            const int q = tid + NTHREADS * i;
            const int k = q >> 5, x = q & 31;
            cp16(sb + k * 512 + ((x ^ (((k >> 3) & 3) << 1)) << 4),
                 W + (kb + (size_t)k) * N_COLS + x * 4);
        }
    };

    // prologue: stages 0..2
    #pragma unroll
    for (int s = 0; s < STAGES - 1; ++s) {
        issue(s, s);   // cnt >= 885 >> 3, always valid
        asm volatile("cp.async.commit_group;" ::: "memory");
    }

    float d[4][4][4];
    #pragma unroll
    for (int a = 0; a < 4; ++a)
        #pragma unroll
        for (int b = 0; b < 4; ++b)
            #pragma unroll
            for (int e = 0; e < 4; ++e) d[a][b][e] = 0.f;

    for (int t = 0; t < cnt; ++t) {
        asm volatile("cp.async.wait_group 2;" ::: "memory");
        __syncthreads();

        const uint32_t sa = sbase + (t & (STAGES - 1)) * STAGE_BYTES;
        const uint32_t sb = sa + 16384;

        // ---- B fragments: bf[nt][j][{b0,b1}], k = 8c + 2j (+1) ----
        uint32_t bf[4][4][2];
        #pragma unroll
        for (int nt = 0; nt < 4; ++nt) {
            const int n = wn * 32 + nt * 8 + r4;
            const uint32_t baddr = sb + (((n >> 2) ^ (2 * c)) << 4) + (n & 3) * 4;
            #pragma unroll
            for (int j = 0; j < 4; ++j) {
                const int k0 = 8 * c + 2 * j;
                bf[nt][j][0] = f2tf32(lds32(baddr + k0 * 512));
                bf[nt][j][1] = f2tf32(lds32(baddr + (k0 + 1) * 512));
            }
        }

        // ---- A fragments + MMA, one 16-row pair-group (mt) at a time ----
        const uint32_t ch0 = ((2 * c) ^ r4) << 4;
        const uint32_t ch1 = ((2 * c + 1) ^ r4) << 4;
        #pragma unroll
        for (int mt = 0; mt < 4; ++mt) {
            const int R0 = wm * 64 + mt * 16 + r4;
            const uint32_t ab0 = sa + R0 * 128;        // row R0
            const uint32_t ab1 = ab0 + 8 * 128;        // row R0+8
            const float4 p0 = lds128(ab0 + ch0);       // k 8c..8c+3
            const float4 p1 = lds128(ab0 + ch1);       // k 8c+4..8c+7
            const float4 q0 = lds128(ab1 + ch0);
            const float4 q1 = lds128(ab1 + ch1);
            uint32_t a0r[8] = { f2tf32(p0.x), f2tf32(p0.y), f2tf32(p0.z), f2tf32(p0.w),
                                f2tf32(p1.x), f2tf32(p1.y), f2tf32(p1.z), f2tf32(p1.w) };
            uint32_t a1r[8] = { f2tf32(q0.x), f2tf32(q0.y), f2tf32(q0.z), f2tf32(q0.w),
                                f2tf32(q1.x), f2tf32(q1.y), f2tf32(q1.z), f2tf32(q1.w) };
            #pragma unroll
            for (int j = 0; j < 4; ++j) {
                const uint32_t A0 = a0r[2 * j],     A1 = a1r[2 * j];
                const uint32_t A2 = a0r[2 * j + 1], A3 = a1r[2 * j + 1];
                #pragma unroll
                for (int nt = 0; nt < 4; ++nt)
                    mma_tf32(d[mt][nt], A0, A1, A2, A3, bf[nt][j][0], bf[nt][j][1]);
            }
        }

        __syncthreads();
        if (t + STAGES - 1 < cnt) issue((t + STAGES - 1) & (STAGES - 1), t + STAGES - 1);
        asm volatile("cp.async.commit_group;" ::: "memory");
    }

    // ---- epilogue: write 128x128 partial to scratch[kg] ----
    float* outp = g_scratch + (size_t)kg * (M_ROWS * N_COLS);
    #pragma unroll
    for (int mt = 0; mt < 4; ++mt) {
        #pragma unroll
        for (int nt = 0; nt < 4; ++nt) {
            const int row = mg * 128 + wm * 64 + mt * 16 + r4;
            const int col = wn * 32 + nt * 8 + 2 * c;
            float2 v0 = make_float2(d[mt][nt][0], d[mt][nt][1]);
            float2 v1 = make_float2(d[mt][nt][2], d[mt][nt][3]);
            *reinterpret_cast<float2*>(outp + (size_t)row * N_COLS + col)       = v0;
            *reinterpret_cast<float2*>(outp + (size_t)(row + 8) * N_COLS + col) = v1;
        }
    }
}

// ---------------- deterministic 37-way reduction ----------------
__global__ void reduce_partials(float* __restrict__ out) {
    const int i = blockIdx.x * blockDim.x + threadIdx.x;   // 0 .. 65535
    float acc = 0.f;
    #pragma unroll
    for (int g = 0; g < NUM_KG; ++g)
        acc += g_scratch[(size_t)g * (M_ROWS * N_COLS) + i];
    out[i] = acc;
}

extern "C" void kernel_launch(void* const* d_in, const int* in_sizes, int n_in,
                              void* d_out, int out_size) {
    const float* X = (const float*)d_in[0];   // [512, 1024, 1024]
    const float* W = (const float*)d_in[1];   // [1024, 1024, 128]
    float* out = (float*)d_out;               // [512, 128]

    cudaFuncSetAttribute(gemm_tf32_mmasync, cudaFuncAttributeMaxDynamicSharedMemorySize, SMEM_TOTAL);
    gemm_tf32_mmasync<<<NUM_KG * 4, NTHREADS, SMEM_TOTAL>>>(X, W);
    reduce_partials<<<(M_ROWS * N_COLS) / 256, 256>>>(out);
}

// round 11
// speedup vs baseline: 1.5695x; 1.5671x over previous
#include <cuda_runtime.h>
#include <cstdint>

// out[512,128] = X[512, 1048576] @ W[1048576, 128]   fp32 in/out
//
// One kernel symbol, two bodies:
//  - sm_103a-specific pass (feature macro defined): tcgen05 tf32 SS MMA,
//    full 512x128 fp32 accumulator in TMEM, strided split-K over 148 CTAs.
//  - generic pass (compute_103 PTX): proven mma.sync.m16n8k8.tf32 kernel
//    (512 threads, 256x128 CTA tile, 74 split-K groups x 2 M-groups).
// Driver loads the sm_103a cubin when present.

#if defined(__CUDA_ARCH_FEAT_SM103_ALL)
#define USE_TCGEN05 1
#elif defined(__CUDA_ARCH_SPECIFIC__)
#if __CUDA_ARCH_SPECIFIC__ >= 1000
#define USE_TCGEN05 1
#else
#define USE_TCGEN05 0
#endif
#else
#define USE_TCGEN05 0
#endif

#define RED_LEN   1048576
#define M_ROWS    512
#define N_COLS    128
#define KTILE     32
#define NUM_CTAS  148
#define NTHREADS  512

// ---- tcgen05 path smem layout ----
#define SM_TMEMPTR 0
#define SM_BAR0    16
#define SM_BAR1    24
#define SM_A_OFF   1024
#define SM_A_STAGE 65536                 // 4 subtiles x (128 rows x 128B)
#define SM_B_OFF   (1024 + 2*65536)
#define SM_B_STAGE 16384                 // 128 N-rows x 128B (K-major)
#define SMEM_TOTAL (1024 + 2*65536 + 2*16384)   // 164864 (>= fallback's 147456)

// tcgen05 split-K: 32768 k-tiles = 148*221 + 60
#define TC_BASE 221
#define TC_REM  60

// fallback split-K: 74 groups x 2 M-groups; 32768 = 74*442 + 60
#define FB_BASE 442
#define FB_REM  60
#define FB_STAGE_BYTES 49152             // A 32KB (256x32 f32) + B 16KB

// idesc kind::tf32 SS cg1: c=F32(bit4), a=TF32(2<<7), b=TF32(2<<10),
// N>>3=16 (<<17), M>>4=8 (<<24), K-major A/B.
#define IDESC_TF32 0x08200910u

__device__ float g_scratch[(size_t)NUM_CTAS * M_ROWS * N_COLS];  // 38.8 MB, zero-init

// ---------------- shared helpers ----------------
__device__ __forceinline__ uint32_t smem_u32(const void* p) {
    uint32_t a;
    asm("{ .reg .u64 t; cvta.to.shared.u64 t, %1; cvt.u32.u64 %0, t; }" : "=r"(a) : "l"(p));
    return a;
}
__device__ __forceinline__ uint32_t f2tf32(float x) {   // round-to-nearest tf32
    uint32_t u;
    asm("cvt.rna.tf32.f32 %0, %1;" : "=r"(u) : "f"(x));
    return u;
}

#if USE_TCGEN05
// ================= tcgen05 path helpers =================
__device__ __forceinline__ uint32_t elect_one() {
    uint32_t p;
    asm volatile("{ .reg .pred p; elect.sync _|p, 0xFFFFFFFF; selp.b32 %0, 1, 0, p; }" : "=r"(p));
    return p;
}
#define MBARRIER_INIT(addr, cnt) \
    asm volatile("mbarrier.init.shared.b64 [%0], %1;" :: "r"((uint32_t)(addr)), "r"((uint32_t)(cnt)) : "memory")

#define MBARRIER_WAIT_PARITY(mbar_smem_addr, phase_parity) do { \
    uint32_t _mbar = (uint32_t)(mbar_smem_addr); \
    uint32_t _parity = (uint32_t)(phase_parity); \
    uint32_t _done; \
    asm volatile( \
        "{\n\t.reg .pred p;\n\t" \
        "mbarrier.try_wait.parity.acquire.cta.shared::cta.b64 p, [%1], %2;\n\t" \
        "selp.b32 %0, 1, 0, p;\n\t}" \
        : "=r"(_done) : "r"(_mbar), "r"(_parity) : "memory"); \
    if (!_done) { \
        asm volatile( \
            "{\n\t.reg .pred P1;\n\t" \
            "WAIT_LOOP_%=:\n\t" \
            "mbarrier.try_wait.parity.acquire.cta.shared::cta.b64 P1, [%0], %1, 0x989680;\n\t" \
            "@P1 bra.uni WAIT_DONE_%=;\n\t" \
            "bra.uni WAIT_LOOP_%=;\n\t" \
            "WAIT_DONE_%=:\n\t}" \
            :: "r"(_mbar), "r"(_parity) : "memory"); \
    } \
} while (0)

#define TCGEN05_COMMIT(mbar) \
    asm volatile("tcgen05.commit.cta_group::1.mbarrier::arrive::one.shared::cluster.b64 [%0];" \
                 :: "r"((uint32_t)(mbar)) : "memory")
#define TCGEN05_FENCE_AFTER()  asm volatile("tcgen05.fence::after_thread_sync;" ::: "memory")
#define TCGEN05_FENCE_BEFORE() asm volatile("tcgen05.fence::before_thread_sync;" ::: "memory")
#define TCGEN05_WAIT_LD()      asm volatile("tcgen05.wait::ld.sync.aligned;" ::: "memory")

#define TCGEN05_LD_32X32B_X32(r, tmem_addr) \
    asm volatile( \
        "tcgen05.ld.sync.aligned.32x32b.x32.b32 " \
        "{%0, %1, %2, %3, %4, %5, %6, %7, " \
        " %8, %9, %10, %11, %12, %13, %14, %15, " \
        " %16, %17, %18, %19, %20, %21, %22, %23, " \
        " %24, %25, %26, %27, %28, %29, %30, %31}, [%32];" \
        : "=r"((r)[0]),  "=r"((r)[1]),  "=r"((r)[2]),  "=r"((r)[3]), \
          "=r"((r)[4]),  "=r"((r)[5]),  "=r"((r)[6]),  "=r"((r)[7]), \
          "=r"((r)[8]),  "=r"((r)[9]),  "=r"((r)[10]), "=r"((r)[11]), \
          "=r"((r)[12]), "=r"((r)[13]), "=r"((r)[14]), "=r"((r)[15]), \
          "=r"((r)[16]), "=r"((r)[17]), "=r"((r)[18]), "=r"((r)[19]), \
          "=r"((r)[20]), "=r"((r)[21]), "=r"((r)[22]), "=r"((r)[23]), \
          "=r"((r)[24]), "=r"((r)[25]), "=r"((r)[26]), "=r"((r)[27]), \
          "=r"((r)[28]), "=r"((r)[29]), "=r"((r)[30]), "=r"((r)[31]) \
        : "r"(tmem_addr))

// K-major SW128 smem descriptor: 128B rows, SBO=64, LBO=1, version=1
static constexpr uint64_t SMEM_DESC_BASE_SW128 =
    (uint64_t(2)  << 61) | (uint64_t(1) << 46) | (uint64_t(64) << 32) | (uint64_t(1) << 16);
#define MAKE_SMEM_DESC(base_addr) (SMEM_DESC_BASE_SW128 | ((uint64_t)((base_addr) >> 4) & 0x3FFF))

__device__ __forceinline__ void mma_tf32_ss(uint32_t d_tmem, uint64_t a_desc, uint64_t b_desc,
                                            uint32_t idesc, uint32_t enable_d) {
    asm volatile(
        "{\n\t.reg .pred p;\n\t"
        "setp.ne.u32 p, %4, 0;\n\t"
        "tcgen05.mma.cta_group::1.kind::tf32 [%0], %1, %2, %3, {%5,%5,%5,%5}, p;\n\t}"
        :: "r"(d_tmem), "l"(a_desc), "l"(b_desc), "r"(idesc), "r"(enable_d), "r"(0u)
        : "memory");
}

// stage fill: LDG -> cvt.rna.tf32 -> swizzled STS
// A: 4 subtiles x [128 rows x 32 tf32], 128B rows SW128. B: [128 N x 32 k] K-major SW128.
__device__ __forceinline__ void tc_fill(const float* __restrict__ X, const float* __restrict__ W,
                                        char* sA, char* sB, int kred0, int tid) {
    const int lid = tid & 31;
    const int wid = tid >> 5;
    {   // A: warp w covers rows [w*32, w*32+32)
        const int c  = lid & 7;
        const int r0 = wid * 32 + (lid >> 3);
        #pragma unroll
        for (int i = 0; i < 8; ++i) {
            const int row = r0 + i * 4;
            const float4 v = *reinterpret_cast<const float4*>(
                X + (size_t)row * RED_LEN + (size_t)kred0 + c * 4);
            uint4 tv;
            tv.x = f2tf32(v.x); tv.y = f2tf32(v.y); tv.z = f2tf32(v.z); tv.w = f2tf32(v.w);
            const int m = row >> 7, r = row & 127;
            *reinterpret_cast<uint4*>(sA + (m * 16384 + r * 128 + ((c ^ (r & 7)) << 4))) = tv;
        }
    }
    {   // B transpose: [32 x 128] global -> [128 x 32] K-major SMEM
        const int n   = tid & 127;
        const int kb0 = (tid >> 7);
        #pragma unroll
        for (int j = 0; j < 2; ++j) {
            const int kb = kb0 + 4 * j;
            const int kk = kb * 4;
            const float* wp = W + (size_t)(kred0 + kk) * N_COLS + n;
            uint4 tv;
            tv.x = f2tf32(wp[0]);
            tv.y = f2tf32(wp[N_COLS]);
            tv.z = f2tf32(wp[2 * N_COLS]);
            tv.w = f2tf32(wp[3 * N_COLS]);
            *reinterpret_cast<uint4*>(sB + (n * 128 + ((kb ^ (n & 7)) << 4))) = tv;
        }
    }
    asm volatile("fence.proxy.async.shared::cta;" ::: "memory");
}
#else
// ================= mma.sync fallback helpers =================
__device__ __forceinline__ void cp16(uint32_t dst_smem, const void* src) {
    asm volatile("cp.async.cg.shared.global [%0], [%1], 16;" :: "r"(dst_smem), "l"(src) : "memory");
}
__device__ __forceinline__ float4 lds128(uint32_t addr) {
    float4 v;
    asm volatile("ld.shared.v4.f32 {%0,%1,%2,%3}, [%4];"
                 : "=f"(v.x), "=f"(v.y), "=f"(v.z), "=f"(v.w) : "r"(addr));
    return v;
}
__device__ __forceinline__ float lds32(uint32_t addr) {
    float v;
    asm volatile("ld.shared.f32 %0, [%1];" : "=f"(v) : "r"(addr));
    return v;
}
__device__ __forceinline__ void mma_tf32(float d[4], uint32_t a0, uint32_t a1, uint32_t a2, uint32_t a3,
                                         uint32_t b0, uint32_t b1) {
    asm volatile(
        "mma.sync.aligned.m16n8k8.row.col.f32.tf32.tf32.f32 "
        "{%0,%1,%2,%3}, {%4,%5,%6,%7}, {%8,%9}, {%0,%1,%2,%3};"
        : "+f"(d[0]), "+f"(d[1]), "+f"(d[2]), "+f"(d[3])
        : "r"(a0), "r"(a1), "r"(a2), "r"(a3), "r"(b0), "r"(b1));
}
#endif

// ================= unified GEMM kernel =================
__global__ void __launch_bounds__(NTHREADS, 1)
gemm_kernel(const float* __restrict__ X, const float* __restrict__ W) {
    extern __shared__ char smem[];
    const uint32_t sbase = smem_u32(smem);
    const int tid = threadIdx.x;
    const int wid = tid >> 5;
    const int lid = tid & 31;

#if USE_TCGEN05
    // ---------- tcgen05 tf32 SS MMA, 512x128 accumulator in TMEM ----------
    const int cta = blockIdx.x;

    if (wid == 0) {
        asm volatile("tcgen05.alloc.cta_group::1.sync.aligned.shared::cta.b32 [%0], %1;"
                     :: "r"(sbase + SM_TMEMPTR), "r"(512u) : "memory");
        asm volatile("tcgen05.relinquish_alloc_permit.cta_group::1.sync.aligned;");
    }
    if (tid == 0) {
        MBARRIER_INIT(sbase + SM_BAR0, 1);
        MBARRIER_INIT(sbase + SM_BAR1, 1);
    }
    __syncthreads();
    uint32_t tmem;
    asm volatile("ld.shared.b32 %0, [%1];" : "=r"(tmem) : "r"(sbase + SM_TMEMPTR));

    const int ntiles = TC_BASE + (cta < TC_REM ? 1 : 0);   // strided split-K

    tc_fill(X, W, smem + SM_A_OFF,              smem + SM_B_OFF,              cta * KTILE, tid);
    tc_fill(X, W, smem + SM_A_OFF + SM_A_STAGE, smem + SM_B_OFF + SM_B_STAGE, (cta + NUM_CTAS) * KTILE, tid);

    uint32_t ph0 = 0, ph1 = 0;
    for (int t = 0; t < ntiles; ++t) {
        const int s = t & 1;
        __syncthreads();   // stage s data visible (fills done pre-sync + proxy fence)

        if (wid == 0) {
            TCGEN05_FENCE_AFTER();
            if (elect_one()) {
                const uint64_t bd = MAKE_SMEM_DESC(sbase + SM_B_OFF + s * SM_B_STAGE);
                #pragma unroll
                for (int m = 0; m < 4; ++m) {
                    const uint64_t ad = MAKE_SMEM_DESC(sbase + SM_A_OFF + s * SM_A_STAGE + m * 16384);
                    #pragma unroll
                    for (int k = 0; k < 4; ++k) {   // K=8 per dispatch, +32B per step
                        mma_tf32_ss(tmem + m * 128, ad + 2 * k, bd + 2 * k,
                                    IDESC_TF32, (t > 0 || k > 0) ? 1u : 0u);
                    }
                }
                TCGEN05_COMMIT(sbase + (s ? SM_BAR1 : SM_BAR0));
            }
        }

        if (t + 2 < ntiles) {
            if (s) { MBARRIER_WAIT_PARITY(sbase + SM_BAR1, ph1); ph1 ^= 1; }
            else   { MBARRIER_WAIT_PARITY(sbase + SM_BAR0, ph0); ph0 ^= 1; }
            const int g = cta + (t + 2) * NUM_CTAS;
            tc_fill(X, W, smem + SM_A_OFF + s * SM_A_STAGE,
                    smem + SM_B_OFF + s * SM_B_STAGE, g * KTILE, tid);
        }
    }

    MBARRIER_WAIT_PARITY(sbase + SM_BAR0, ph0);
    MBARRIER_WAIT_PARITY(sbase + SM_BAR1, ph1);
    TCGEN05_FENCE_AFTER();

    {   // epilogue: warp w -> subtile m=w>>2 (TMEM col m*128), subpartition g=w&3
        const int m = wid >> 2;
        const int g = wid & 3;
        const int row = m * 128 + g * 32 + lid;
        float* dst = g_scratch + (size_t)cta * (M_ROWS * N_COLS) + (size_t)row * N_COLS;
        #pragma unroll
        for (int c0 = 0; c0 < 128; c0 += 32) {
            uint32_t r[32];
            TCGEN05_LD_32X32B_X32(r, tmem + m * 128 + c0);
            TCGEN05_WAIT_LD();
            #pragma unroll
            for (int j = 0; j < 32; j += 4) {
                float4 v = make_float4(__uint_as_float(r[j]),     __uint_as_float(r[j + 1]),
                                       __uint_as_float(r[j + 2]), __uint_as_float(r[j + 3]));
                *reinterpret_cast<float4*>(dst + c0 + j) = v;
            }
        }
    }

    TCGEN05_FENCE_BEFORE();
    __syncthreads();
    if (wid == 0) {
        asm volatile("tcgen05.dealloc.cta_group::1.sync.aligned.b32 %0, %1;" :: "r"(tmem), "r"(512u));
    }
#else
    // ---------- mma.sync fallback: 256x128 CTA tile, 16 warps 4m x 4n ----------
    const int wm = wid >> 2;            // 0..3, 64 rows each
    const int wn = wid & 3;             // 0..3, 32 cols each
    const int c  = lid & 3;
    const int r4 = lid >> 3;

    const int bid = blockIdx.x;
    const int kg  = bid >> 1;           // 0..73
    const int mg  = bid & 1;            // 0..1, 256 rows each

    const int t0  = kg * FB_BASE + (kg < FB_REM ? kg : FB_REM);
    const int cnt = FB_BASE + (kg < FB_REM ? 1 : 0);
    const float* Xb = X + (size_t)(mg * 256) * RED_LEN;

    auto issue = [&](int stage, int tile) {
        const uint32_t sa = sbase + stage * FB_STAGE_BYTES;
        const uint32_t sb = sa + 32768;
        const size_t kb = (size_t)(t0 + tile) * KTILE;
        #pragma unroll
        for (int i = 0; i < 4; ++i) {          // A: 2048 chunks (256 rows x 8)
            const int q = tid + NTHREADS * i;
            const int row = q >> 3, x = q & 7;
            cp16(sa + row * 128 + ((x ^ (row & 7)) << 4),
                 Xb + (size_t)row * RED_LEN + kb + x * 4);
        }
        #pragma unroll
        for (int i = 0; i < 2; ++i) {          // B: 1024 chunks (32 k-rows x 32)
            const int q = tid + NTHREADS * i;
            const int k = q >> 5, x = q & 31;
            cp16(sb + k * 512 + ((x ^ (((k >> 3) & 3) << 1)) << 4),
                 W + (kb + (size_t)k) * N_COLS + x * 4);
        }
    };

    #pragma unroll
    for (int s = 0; s < 2; ++s) {              // 3-stage pipeline prologue
        issue(s, s);
        asm volatile("cp.async.commit_group;" ::: "memory");
    }

    float d[4][4][4];
    #pragma unroll
    for (int a = 0; a < 4; ++a)
        #pragma unroll
        for (int b = 0; b < 4; ++b)
            #pragma unroll
            for (int e = 0; e < 4; ++e) d[a][b][e] = 0.f;

    int st = 0;
    for (int t = 0; t < cnt; ++t) {
        asm volatile("cp.async.wait_group 1;" ::: "memory");
        __syncthreads();

        const uint32_t sa = sbase + st * FB_STAGE_BYTES;
        const uint32_t sb = sa + 32768;

        uint32_t bf[4][4][2];
        #pragma unroll
        for (int nt = 0; nt < 4; ++nt) {
            const int n = wn * 32 + nt * 8 + r4;
            const uint32_t baddr = sb + (((n >> 2) ^ (2 * c)) << 4) + (n & 3) * 4;
            #pragma unroll
            for (int j = 0; j < 4; ++j) {
                const int k0 = 8 * c + 2 * j;
                bf[nt][j][0] = f2tf32(lds32(baddr + k0 * 512));
                bf[nt][j][1] = f2tf32(lds32(baddr + (k0 + 1) * 512));
            }
        }

        const uint32_t ch0 = ((2 * c) ^ r4) << 4;
        const uint32_t ch1 = ((2 * c + 1) ^ r4) << 4;
        #pragma unroll
        for (int mt = 0; mt < 4; ++mt) {
            const int R0 = wm * 64 + mt * 16 + r4;
            const uint32_t ab0 = sa + R0 * 128;
            const uint32_t ab1 = ab0 + 8 * 128;
            const float4 p0 = lds128(ab0 + ch0);
            const float4 p1 = lds128(ab0 + ch1);
            const float4 q0 = lds128(ab1 + ch0);
            const float4 q1 = lds128(ab1 + ch1);
            uint32_t a0r[8] = { f2tf32(p0.x), f2tf32(p0.y), f2tf32(p0.z), f2tf32(p0.w),
                                f2tf32(p1.x), f2tf32(p1.y), f2tf32(p1.z), f2tf32(p1.w) };
            uint32_t a1r[8] = { f2tf32(q0.x), f2tf32(q0.y), f2tf32(q0.z), f2tf32(q0.w),
                                f2tf32(q1.x), f2tf32(q1.y), f2tf32(q1.z), f2tf32(q1.w) };
            #pragma unroll
            for (int j = 0; j < 4; ++j) {
                const uint32_t A0 = a0r[2 * j],     A1 = a1r[2 * j];
                const uint32_t A2 = a0r[2 * j + 1], A3 = a1r[2 * j + 1];
                #pragma unroll
                for (int nt = 0; nt < 4; ++nt)
                    mma_tf32(d[mt][nt], A0, A1, A2, A3, bf[nt][j][0], bf[nt][j][1]);
            }
        }

        __syncthreads();
        if (t + 2 < cnt) {
            int s2 = st + 2; if (s2 >= 3) s2 -= 3;
            issue(s2, t + 2);
        }
        asm volatile("cp.async.commit_group;" ::: "memory");
        if (++st == 3) st = 0;
    }

    // epilogue: slot = bid, rows mg*256.. (uncovered rows stay zero-initialized)
    float* outp = g_scratch + (size_t)bid * (M_ROWS * N_COLS);
    #pragma unroll
    for (int mt = 0; mt < 4; ++mt) {
        #pragma unroll
        for (int nt = 0; nt < 4; ++nt) {
            const int row = mg * 256 + wm * 64 + mt * 16 + r4;
            const int col = wn * 32 + nt * 8 + 2 * c;
            float2 v0 = make_float2(d[mt][nt][0], d[mt][nt][1]);
            float2 v1 = make_float2(d[mt][nt][2], d[mt][nt][3]);
            *reinterpret_cast<float2*>(outp + (size_t)row * N_COLS + col)       = v0;
            *reinterpret_cast<float2*>(outp + (size_t)(row + 8) * N_COLS + col) = v1;
        }
    }
#endif
}

// ---------------- deterministic 148-way reduction ----------------
__global__ void reduce_partials(float* __restrict__ out) {
    const int i = blockIdx.x * blockDim.x + threadIdx.x;   // 0 .. 65535
    float acc = 0.f;
    #pragma unroll 4
    for (int g = 0; g < NUM_CTAS; ++g)
        acc += g_scratch[(size_t)g * (M_ROWS * N_COLS) + i];
    out[i] = acc;
}

extern "C" void kernel_launch(void* const* d_in, const int* in_sizes, int n_in,
                              void* d_out, int out_size) {
    const float* X = (const float*)d_in[0];   // [512, 1024, 1024]
    const float* W = (const float*)d_in[1];   // [1024, 1024, 128]
    float* out = (float*)d_out;               // [512, 128]

    cudaFuncSetAttribute(gemm_kernel, cudaFuncAttributeMaxDynamicSharedMemorySize, SMEM_TOTAL);
    gemm_kernel<<<NUM_CTAS, NTHREADS, SMEM_TOTAL>>>(X, W);
    reduce_partials<<<(M_ROWS * N_COLS) / 256, 256>>>(out);
}

// round 12
// speedup vs baseline: 1.7619x; 1.1226x over previous
#include <cuda_runtime.h>
#include <cstdint>

// out[512,128] = X[512, 1048576] @ W[1048576, 128]   fp32 in/out
//
// One kernel symbol, two bodies:
//  - sm_103a-specific pass: tcgen05 tf32 SS MMA, 512x128 fp32 accumulator in
//    TMEM, strided split-K over 148 CTAs, register-prefetched fill pipeline.
//  - generic compute_103 pass: mma.sync.m16n8k8.tf32 fallback (proven R10).

#if defined(__CUDA_ARCH_FEAT_SM103_ALL)
#define USE_TCGEN05 1
#elif defined(__CUDA_ARCH_SPECIFIC__)
#if __CUDA_ARCH_SPECIFIC__ >= 1000
#define USE_TCGEN05 1
#else
#define USE_TCGEN05 0
#endif
#else
#define USE_TCGEN05 0
#endif

#define RED_LEN   1048576
#define M_ROWS    512
#define N_COLS    128
#define KTILE     32
#define NUM_CTAS  148
#define NTHREADS  512

// ---- tcgen05 path smem layout ----
#define SM_TMEMPTR 0
#define SM_BAR0    16
#define SM_BAR1    24
#define SM_A_OFF   1024
#define SM_A_STAGE 65536                 // 4 subtiles x (128 rows x 128B)
#define SM_B_OFF   (1024 + 2*65536)
#define SM_B_STAGE 16384                 // 128 N-rows x 128B (K-major)
#define SMEM_TOTAL (1024 + 2*65536 + 2*16384)   // 164864

// tcgen05 split-K: 32768 k-tiles = 148*221 + 60
#define TC_BASE 221
#define TC_REM  60

// fallback split-K: 74 groups x 2 M-groups; 32768 = 74*442 + 60
#define FB_BASE 442
#define FB_REM  60
#define FB_STAGE_BYTES 49152             // A 32KB (256x32 f32) + B 16KB

// idesc kind::tf32 SS cg1: c=F32(bit4), a=TF32(2<<7), b=TF32(2<<10),
// N>>3=16 (<<17), M>>4=8 (<<24), K-major A/B.
#define IDESC_TF32 0x08200910u

__device__ float g_scratch[(size_t)NUM_CTAS * M_ROWS * N_COLS];  // 38.8 MB, zero-init

// ---------------- shared helpers ----------------
__device__ __forceinline__ uint32_t smem_u32(const void* p) {
    uint32_t a;
    asm("{ .reg .u64 t; cvta.to.shared.u64 t, %1; cvt.u32.u64 %0, t; }" : "=r"(a) : "l"(p));
    return a;
}
__device__ __forceinline__ uint32_t f2tf32(float x) {   // round-to-nearest tf32
    uint32_t u;
    asm("cvt.rna.tf32.f32 %0, %1;" : "=r"(u) : "f"(x));
    return u;
}

#if USE_TCGEN05
// ================= tcgen05 path helpers =================
__device__ __forceinline__ uint32_t elect_one() {
    uint32_t p;
    asm volatile("{ .reg .pred p; elect.sync _|p, 0xFFFFFFFF; selp.b32 %0, 1, 0, p; }" : "=r"(p));
    return p;
}
#define MBARRIER_INIT(addr, cnt) \
    asm volatile("mbarrier.init.shared.b64 [%0], %1;" :: "r"((uint32_t)(addr)), "r"((uint32_t)(cnt)) : "memory")

#define MBARRIER_WAIT_PARITY(mbar_smem_addr, phase_parity) do { \
    uint32_t _mbar = (uint32_t)(mbar_smem_addr); \
    uint32_t _parity = (uint32_t)(phase_parity); \
    uint32_t _done; \
    asm volatile( \
        "{\n\t.reg .pred p;\n\t" \
        "mbarrier.try_wait.parity.acquire.cta.shared::cta.b64 p, [%1], %2;\n\t" \
        "selp.b32 %0, 1, 0, p;\n\t}" \
        : "=r"(_done) : "r"(_mbar), "r"(_parity) : "memory"); \
    if (!_done) { \
        asm volatile( \
            "{\n\t.reg .pred P1;\n\t" \
            "WAIT_LOOP_%=:\n\t" \
            "mbarrier.try_wait.parity.acquire.cta.shared::cta.b64 P1, [%0], %1, 0x989680;\n\t" \
            "@P1 bra.uni WAIT_DONE_%=;\n\t" \
            "bra.uni WAIT_LOOP_%=;\n\t" \
            "WAIT_DONE_%=:\n\t}" \
            :: "r"(_mbar), "r"(_parity) : "memory"); \
    } \
} while (0)

#define TCGEN05_COMMIT(mbar) \
    asm volatile("tcgen05.commit.cta_group::1.mbarrier::arrive::one.shared::cluster.b64 [%0];" \
                 :: "r"((uint32_t)(mbar)) : "memory")
#define TCGEN05_FENCE_AFTER()  asm volatile("tcgen05.fence::after_thread_sync;" ::: "memory")
#define TCGEN05_FENCE_BEFORE() asm volatile("tcgen05.fence::before_thread_sync;" ::: "memory")
#define TCGEN05_WAIT_LD()      asm volatile("tcgen05.wait::ld.sync.aligned;" ::: "memory")

#define TCGEN05_LD_32X32B_X32(r, tmem_addr) \
    asm volatile( \
        "tcgen05.ld.sync.aligned.32x32b.x32.b32 " \
        "{%0, %1, %2, %3, %4, %5, %6, %7, " \
        " %8, %9, %10, %11, %12, %13, %14, %15, " \
        " %16, %17, %18, %19, %20, %21, %22, %23, " \
        " %24, %25, %26, %27, %28, %29, %30, %31}, [%32];" \
        : "=r"((r)[0]),  "=r"((r)[1]),  "=r"((r)[2]),  "=r"((r)[3]), \
          "=r"((r)[4]),  "=r"((r)[5]),  "=r"((r)[6]),  "=r"((r)[7]), \
          "=r"((r)[8]),  "=r"((r)[9]),  "=r"((r)[10]), "=r"((r)[11]), \
          "=r"((r)[12]), "=r"((r)[13]), "=r"((r)[14]), "=r"((r)[15]), \
          "=r"((r)[16]), "=r"((r)[17]), "=r"((r)[18]), "=r"((r)[19]), \
          "=r"((r)[20]), "=r"((r)[21]), "=r"((r)[22]), "=r"((r)[23]), \
          "=r"((r)[24]), "=r"((r)[25]), "=r"((r)[26]), "=r"((r)[27]), \
          "=r"((r)[28]), "=r"((r)[29]), "=r"((r)[30]), "=r"((r)[31]) \
        : "r"(tmem_addr))

// K-major SW128 smem descriptor: 128B rows, SBO=64, LBO=1, version=1
static constexpr uint64_t SMEM_DESC_BASE_SW128 =
    (uint64_t(2)  << 61) | (uint64_t(1) << 46) | (uint64_t(64) << 32) | (uint64_t(1) << 16);
#define MAKE_SMEM_DESC(base_addr) (SMEM_DESC_BASE_SW128 | ((uint64_t)((base_addr) >> 4) & 0x3FFF))

__device__ __forceinline__ void mma_tf32_ss(uint32_t d_tmem, uint64_t a_desc, uint64_t b_desc,
                                            uint32_t idesc, uint32_t enable_d) {
    asm volatile(
        "{\n\t.reg .pred p;\n\t"
        "setp.ne.u32 p, %4, 0;\n\t"
        "tcgen05.mma.cta_group::1.kind::tf32 [%0], %1, %2, %3, {%5,%5,%5,%5}, p;\n\t}"
        :: "r"(d_tmem), "l"(a_desc), "l"(b_desc), "r"(idesc), "r"(enable_d), "r"(0u)
        : "memory");
}

// Register-staged tile: A 8x float4 (this thread's 8 rows x 16B chunk),
// B 2x float4 (transposed k-quads).  40 regs.
struct TileRegs {
    float4 a[8];
    float4 b[2];
};

// Issue global loads for k-tile at kred0 into registers (no smem touched).
__device__ __forceinline__ void tc_load(TileRegs& R, const float* __restrict__ X,
                                        const float* __restrict__ W, int kred0, int tid) {
    const int lid = tid & 31;
    const int wid = tid >> 5;
    {   // A: warp w covers rows [w*32, w*32+32); coalesced 128B per (row,i)
        const int c  = lid & 7;
        const int r0 = wid * 32 + (lid >> 3);
        #pragma unroll
        for (int i = 0; i < 8; ++i) {
            const int row = r0 + i * 4;
            R.a[i] = *reinterpret_cast<const float4*>(
                X + (size_t)row * RED_LEN + (size_t)kred0 + c * 4);
        }
    }
    {   // B: lanes n consecutive -> 128B coalesced; 4 k-rows per float4
        const int n   = tid & 127;
        const int kb0 = (tid >> 7);
        #pragma unroll
        for (int j = 0; j < 2; ++j) {
            const int kk = (kb0 + 4 * j) * 4;
            const float* wp = W + (size_t)(kred0 + kk) * N_COLS + n;
            R.b[j] = make_float4(wp[0], wp[N_COLS], wp[2 * N_COLS], wp[3 * N_COLS]);
        }
    }
}

// cvt.rna.tf32 + swizzled STS into stage buffers (conflict-free patterns).
__device__ __forceinline__ void tc_store(const TileRegs& R, char* sA, char* sB, int tid) {
    const int lid = tid & 31;
    const int wid = tid >> 5;
    {
        const int c  = lid & 7;
        const int r0 = wid * 32 + (lid >> 3);
        #pragma unroll
        for (int i = 0; i < 8; ++i) {
            const int row = r0 + i * 4;
            uint4 tv;
            tv.x = f2tf32(R.a[i].x); tv.y = f2tf32(R.a[i].y);
            tv.z = f2tf32(R.a[i].z); tv.w = f2tf32(R.a[i].w);
            const int m = row >> 7, r = row & 127;
            *reinterpret_cast<uint4*>(sA + (m * 16384 + r * 128 + ((c ^ (r & 7)) << 4))) = tv;
        }
    }
    {
        const int n   = tid & 127;
        const int kb0 = (tid >> 7);
        #pragma unroll
        for (int j = 0; j < 2; ++j) {
            const int kb = kb0 + 4 * j;
            uint4 tv;
            tv.x = f2tf32(R.b[j].x); tv.y = f2tf32(R.b[j].y);
            tv.z = f2tf32(R.b[j].z); tv.w = f2tf32(R.b[j].w);
            *reinterpret_cast<uint4*>(sB + (n * 128 + ((kb ^ (n & 7)) << 4))) = tv;
        }
    }
    asm volatile("fence.proxy.async.shared::cta;" ::: "memory");
}
#else
// ================= mma.sync fallback helpers =================
__device__ __forceinline__ void cp16(uint32_t dst_smem, const void* src) {
    asm volatile("cp.async.cg.shared.global [%0], [%1], 16;" :: "r"(dst_smem), "l"(src) : "memory");
}
__device__ __forceinline__ float4 lds128(uint32_t addr) {
    float4 v;
    asm volatile("ld.shared.v4.f32 {%0,%1,%2,%3}, [%4];"
                 : "=f"(v.x), "=f"(v.y), "=f"(v.z), "=f"(v.w) : "r"(addr));
    return v;
}
__device__ __forceinline__ float lds32(uint32_t addr) {
    float v;
    asm volatile("ld.shared.f32 %0, [%1];" : "=f"(v) : "r"(addr));
    return v;
}
__device__ __forceinline__ void mma_tf32(float d[4], uint32_t a0, uint32_t a1, uint32_t a2, uint32_t a3,
                                         uint32_t b0, uint32_t b1) {
    asm volatile(
        "mma.sync.aligned.m16n8k8.row.col.f32.tf32.tf32.f32 "
        "{%0,%1,%2,%3}, {%4,%5,%6,%7}, {%8,%9}, {%0,%1,%2,%3};"
        : "+f"(d[0]), "+f"(d[1]), "+f"(d[2]), "+f"(d[3])
        : "r"(a0), "r"(a1), "r"(a2), "r"(a3), "r"(b0), "r"(b1));
}
#endif

// ================= unified GEMM kernel =================
__global__ void __launch_bounds__(NTHREADS, 1)
gemm_kernel(const float* __restrict__ X, const float* __restrict__ W) {
    extern __shared__ char smem[];
    const uint32_t sbase = smem_u32(smem);
    const int tid = threadIdx.x;
    const int wid = tid >> 5;
    const int lid = tid & 31;

#if USE_TCGEN05
    // ---------- tcgen05 tf32 SS MMA, 512x128 accumulator in TMEM ----------
    const int cta = blockIdx.x;

    if (wid == 0) {
        asm volatile("tcgen05.alloc.cta_group::1.sync.aligned.shared::cta.b32 [%0], %1;"
                     :: "r"(sbase + SM_TMEMPTR), "r"(512u) : "memory");
        asm volatile("tcgen05.relinquish_alloc_permit.cta_group::1.sync.aligned;");
    }
    if (tid == 0) {
        MBARRIER_INIT(sbase + SM_BAR0, 1);
        MBARRIER_INIT(sbase + SM_BAR1, 1);
    }
    __syncthreads();
    uint32_t tmem;
    asm volatile("ld.shared.b32 %0, [%1];" : "=r"(tmem) : "r"(sbase + SM_TMEMPTR));

    const int ntiles = TC_BASE + (cta < TC_REM ? 1 : 0);   // strided split-K (>= 221)

    char* sA0 = smem + SM_A_OFF;
    char* sA1 = smem + SM_A_OFF + SM_A_STAGE;
    char* sB0 = smem + SM_B_OFF;
    char* sB1 = smem + SM_B_OFF + SM_B_STAGE;

    // prologue: tiles 0,1 into stages; tile 2 into registers
    TileRegs R;
    tc_load(R, X, W, cta * KTILE, tid);                 tc_store(R, sA0, sB0, tid);
    tc_load(R, X, W, (cta + NUM_CTAS) * KTILE, tid);    tc_store(R, sA1, sB1, tid);
    tc_load(R, X, W, (cta + 2 * NUM_CTAS) * KTILE, tid);

    uint32_t ph0 = 0, ph1 = 0;
    for (int t = 0; t < ntiles; ++t) {
        const int s = t & 1;
        __syncthreads();   // STS for tile t (stage s) complete across CTA

        if (wid == 0) {
            TCGEN05_FENCE_AFTER();
            if (elect_one()) {
                const uint64_t bd = MAKE_SMEM_DESC(sbase + SM_B_OFF + s * SM_B_STAGE);
                #pragma unroll
                for (int m = 0; m < 4; ++m) {
                    const uint64_t ad = MAKE_SMEM_DESC(sbase + SM_A_OFF + s * SM_A_STAGE + m * 16384);
                    #pragma unroll
                    for (int k = 0; k < 4; ++k) {   // K=8 per dispatch, +32B per step
                        mma_tf32_ss(tmem + m * 128, ad + 2 * k, bd + 2 * k,
                                    IDESC_TF32, (t > 0 || k > 0) ? 1u : 0u);
                    }
                }
                TCGEN05_COMMIT(sbase + (s ? SM_BAR1 : SM_BAR0));
            }
        }

        if (t + 2 < ntiles) {
            // wait until MMA(t) has consumed stage s, then store prefetched
            // tile t+2 (already in registers -> DRAM latency fully hidden)
            if (s) { MBARRIER_WAIT_PARITY(sbase + SM_BAR1, ph1); ph1 ^= 1; }
            else   { MBARRIER_WAIT_PARITY(sbase + SM_BAR0, ph0); ph0 ^= 1; }
            tc_store(R, s ? sA1 : sA0, s ? sB1 : sB0, tid);
            if (t + 3 < ntiles)
                tc_load(R, X, W, (cta + (t + 3) * NUM_CTAS) * KTILE, tid);
        }
    }

    MBARRIER_WAIT_PARITY(sbase + SM_BAR0, ph0);
    MBARRIER_WAIT_PARITY(sbase + SM_BAR1, ph1);
    TCGEN05_FENCE_AFTER();

    {   // epilogue: warp w -> subtile m=w>>2 (TMEM col m*128), subpartition g=w&3
        const int m = wid >> 2;
        const int g = wid & 3;
        const int row = m * 128 + g * 32 + lid;
        float* dst = g_scratch + (size_t)cta * (M_ROWS * N_COLS) + (size_t)row * N_COLS;
        #pragma unroll
        for (int c0 = 0; c0 < 128; c0 += 32) {
            uint32_t r[32];
            TCGEN05_LD_32X32B_X32(r, tmem + m * 128 + c0);
            TCGEN05_WAIT_LD();
            #pragma unroll
            for (int j = 0; j < 32; j += 4) {
                float4 v = make_float4(__uint_as_float(r[j]),     __uint_as_float(r[j + 1]),
                                       __uint_as_float(r[j + 2]), __uint_as_float(r[j + 3]));
                *reinterpret_cast<float4*>(dst + c0 + j) = v;
            }
        }
    }

    TCGEN05_FENCE_BEFORE();
    __syncthreads();
    if (wid == 0) {
        asm volatile("tcgen05.dealloc.cta_group::1.sync.aligned.b32 %0, %1;" :: "r"(tmem), "r"(512u));
    }
#else
    // ---------- mma.sync fallback: 256x128 CTA tile, 16 warps 4m x 4n ----------
    const int wm = wid >> 2;
    const int wn = wid & 3;
    const int c  = lid & 3;
    const int r4 = lid >> 3;

    const int bid = blockIdx.x;
    const int kg  = bid >> 1;
    const int mg  = bid & 1;

    const int t0  = kg * FB_BASE + (kg < FB_REM ? kg : FB_REM);
    const int cnt = FB_BASE + (kg < FB_REM ? 1 : 0);
    const float* Xb = X + (size_t)(mg * 256) * RED_LEN;

    auto issue = [&](int stage, int tile) {
        const uint32_t sa = sbase + stage * FB_STAGE_BYTES;
        const uint32_t sb = sa + 32768;
        const size_t kb = (size_t)(t0 + tile) * KTILE;
        #pragma unroll
        for (int i = 0; i < 4; ++i) {
            const int q = tid + NTHREADS * i;
            const int row = q >> 3, x = q & 7;
            cp16(sa + row * 128 + ((x ^ (row & 7)) << 4),
                 Xb + (size_t)row * RED_LEN + kb + x * 4);
        }
        #pragma unroll
        for (int i = 0; i < 2; ++i) {
            const int q = tid + NTHREADS * i;
            const int k = q >> 5, x = q & 31;
            cp16(sb + k * 512 + ((x ^ (((k >> 3) & 3) << 1)) << 4),
                 W + (kb + (size_t)k) * N_COLS + x * 4);
        }
    };

    #pragma unroll
    for (int s = 0; s < 2; ++s) {
        issue(s, s);
        asm volatile("cp.async.commit_group;" ::: "memory");
    }

    float d[4][4][4];
    #pragma unroll
    for (int a = 0; a < 4; ++a)
        #pragma unroll
        for (int b = 0; b < 4; ++b)
            #pragma unroll
            for (int e = 0; e < 4; ++e) d[a][b][e] = 0.f;

    int st = 0;
    for (int t = 0; t < cnt; ++t) {
        asm volatile("cp.async.wait_group 1;" ::: "memory");
        __syncthreads();

        const uint32_t sa = sbase + st * FB_STAGE_BYTES;
        const uint32_t sb = sa + 32768;

        uint32_t bf[4][4][2];
        #pragma unroll
        for (int nt = 0; nt < 4; ++nt) {
            const int n = wn * 32 + nt * 8 + r4;
            const uint32_t baddr = sb + (((n >> 2) ^ (2 * c)) << 4) + (n & 3) * 4;
            #pragma unroll
            for (int j = 0; j < 4; ++j) {
                const int k0 = 8 * c + 2 * j;
                bf[nt][j][0] = f2tf32(lds32(baddr + k0 * 512));
                bf[nt][j][1] = f2tf32(lds32(baddr + (k0 + 1) * 512));
            }
        }

        const uint32_t ch0 = ((2 * c) ^ r4) << 4;
        const uint32_t ch1 = ((2 * c + 1) ^ r4) << 4;
        #pragma unroll
        for (int mt = 0; mt < 4; ++mt) {
            const int R0 = wm * 64 + mt * 16 + r4;
            const uint32_t ab0 = sa + R0 * 128;
            const uint32_t ab1 = ab0 + 8 * 128;
            const float4 p0 = lds128(ab0 + ch0);
            const float4 p1 = lds128(ab0 + ch1);
            const float4 q0 = lds128(ab1 + ch0);
            const float4 q1 = lds128(ab1 + ch1);
            uint32_t a0r[8] = { f2tf32(p0.x), f2tf32(p0.y), f2tf32(p0.z), f2tf32(p0.w),
                                f2tf32(p1.x), f2tf32(p1.y), f2tf32(p1.z), f2tf32(p1.w) };
            uint32_t a1r[8] = { f2tf32(q0.x), f2tf32(q0.y), f2tf32(q0.z), f2tf32(q0.w),
                                f2tf32(q1.x), f2tf32(q1.y), f2tf32(q1.z), f2tf32(q1.w) };
            #pragma unroll
            for (int j = 0; j < 4; ++j) {
                const uint32_t A0 = a0r[2 * j],     A1 = a1r[2 * j];
                const uint32_t A2 = a0r[2 * j + 1], A3 = a1r[2 * j + 1];
                #pragma unroll
                for (int nt = 0; nt < 4; ++nt)
                    mma_tf32(d[mt][nt], A0, A1, A2, A3, bf[nt][j][0], bf[nt][j][1]);
            }
        }

        __syncthreads();
        if (t + 2 < cnt) {
            int s2 = st + 2; if (s2 >= 3) s2 -= 3;
            issue(s2, t + 2);
        }
        asm volatile("cp.async.commit_group;" ::: "memory");
        if (++st == 3) st = 0;
    }

    float* outp = g_scratch + (size_t)bid * (M_ROWS * N_COLS);
    #pragma unroll
    for (int mt = 0; mt < 4; ++mt) {
        #pragma unroll
        for (int nt = 0; nt < 4; ++nt) {
            const int row = mg * 256 + wm * 64 + mt * 16 + r4;
            const int col = wn * 32 + nt * 8 + 2 * c;
            float2 v0 = make_float2(d[mt][nt][0], d[mt][nt][1]);
            float2 v1 = make_float2(d[mt][nt][2], d[mt][nt][3]);
            *reinterpret_cast<float2*>(outp + (size_t)row * N_COLS + col)       = v0;
            *reinterpret_cast<float2*>(outp + (size_t)(row + 8) * N_COLS + col) = v1;
        }
    }
#endif
}

// ---------------- deterministic 148-way reduction (vectorized) ----------------
__global__ void reduce_partials(float* __restrict__ out) {
    const int i4 = blockIdx.x * blockDim.x + threadIdx.x;   // 0 .. 16383 (float4 units)
    const float4* src = reinterpret_cast<const float4*>(g_scratch);
    float4 acc = make_float4(0.f, 0.f, 0.f, 0.f);
    #pragma unroll 4
    for (int g = 0; g < NUM_CTAS; ++g) {
        const float4 v = src[(size_t)g * (M_ROWS * N_COLS / 4) + i4];
        acc.x += v.x; acc.y += v.y; acc.z += v.z; acc.w += v.w;
    }
    reinterpret_cast<float4*>(out)[i4] = acc;
}

extern "C" void kernel_launch(void* const* d_in, const int* in_sizes, int n_in,
                              void* d_out, int out_size) {
    const float* X = (const float*)d_in[0];   // [512, 1024, 1024]
    const float* W = (const float*)d_in[1];   // [1024, 1024, 128]
    float* out = (float*)d_out;               // [512, 128]

    cudaFuncSetAttribute(gemm_kernel, cudaFuncAttributeMaxDynamicSharedMemorySize, SMEM_TOTAL);
    gemm_kernel<<<NUM_CTAS, NTHREADS, SMEM_TOTAL>>>(X, W);
    reduce_partials<<<(M_ROWS * N_COLS / 4) / 256, 256>>>(out);
}